// round 14
// baseline (speedup 1.0000x reference)
#include <cuda_runtime.h>
#include <math.h>

#define BB    16
#define MMM   1024
#define NN    512
#define CC    8
#define COUT  64
#define NWARP 16              // warps per CTA
#define NSUB  (NWARP * 2)     // 32 half-warp n-slices
#define NPS   (NN / NSUB)     // 16 n per slice
#define MPB   64              // m per CTA (4 per lane, 16 lanes per half)
#define TPB   (32 * NWARP)    // 512 threads

__device__ __forceinline__ float ex2f(float x) {
    float y;
    asm("ex2.approx.ftz.f32 %0, %1;" : "=f"(y) : "f"(x));
    return y;
}
__device__ __forceinline__ unsigned long long pack2(float lo, float hi) {
    unsigned long long r;
    asm("mov.b64 %0, {%1, %2};" : "=l"(r) : "f"(lo), "f"(hi));
    return r;
}
__device__ __forceinline__ void unpack2(unsigned long long v, float& lo, float& hi) {
    asm("mov.b64 {%0, %1}, %2;" : "=f"(lo), "=f"(hi) : "l"(v));
}
__device__ __forceinline__ void ffma2(unsigned long long& d, unsigned long long a, unsigned long long b) {
    asm("fma.rn.f32x2 %0, %1, %2, %0;" : "+l"(d) : "l"(a), "l"(b));
}

__global__ __launch_bounds__(TPB, 2)   // cap regs at 64 -> 2 CTAs/SM
void convdeepset_kernel(const float* __restrict__ ci,    // (B,N,1)
                        const float* __restrict__ co,    // (B,N,7)
                        const float* __restrict__ ti,    // (B,M,1)
                        const float* __restrict__ sigma, // (8,)
                        const float* __restrict__ W,     // (64,8)
                        const float* __restrict__ bias,  // (64,)
                        float* __restrict__ out)         // (B,M,64)
{
    __shared__ float4      s_ab2[NN / 2];            // 4KB: (a_n,b_n,a_{n+1},b_{n+1})
    __shared__ ulonglong2  s_cx[NN * 2];             // 16KB: packed f32x2 channels
    __shared__ float       s_part[NWARP][CC][MPB];   // 32KB: per-warp partials (post-shfl)
    __shared__ float       s_v[CC][MPB];             // 2KB
    __shared__ float       s_dens[MPB];
    __shared__ float       s_Wt[CC][COUT];
    __shared__ float       s_bias[COUT];

    const int tid  = threadIdx.x;
    const int w    = tid >> 5;
    const int lane = tid & 31;
    const int s    = lane >> 4;          // half-warp n-subslice (0/1)
    const int ml   = lane & 15;          // local m seed (4 m's: ml + 16k)
    const int v    = w * 2 + s;          // virtual slice 0..31
    const int blk  = blockIdx.x;
    const int b    = blk >> 4;           // 16 m-tiles of 64 per batch
    const int mt   = blk & 15;
    const int mbase = mt * MPB;

    // stage W^T + bias
    if (tid < CC * COUT) {
        int o = tid / CC, c = tid % CC;
        s_Wt[c][o] = W[tid];
    }
    if (tid < COUT) s_bias[tid] = bias[tid];

    // uniform-sigma detection
    const float LOG2E = 1.4426950408889634f;
    float sg0 = sigma[0];
    bool uni = true;
    #pragma unroll
    for (int c = 1; c < CC; c++) uni &= (sigma[c] == sg0);
    const float k2u = -0.5f * LOG2E * expf(-2.0f * sg0);

    // stage context rows (1 per thread)
    const float* cib = ci + (size_t)b * NN;
    const float* cob = co + (size_t)b * NN * 7;
    float2* s_abf2 = (float2*)s_ab2;
    {
        int i = tid;
        float x = cib[i];
        float2 ab;
        if (uni) { ab.x = k2u * x * x; ab.y = -2.0f * k2u * x; }
        else     { ab.x = x;           ab.y = 0.0f; }
        s_abf2[i] = ab;
        const float* r = cob + i * 7;
        s_cx[2 * i]     = make_ulonglong2(pack2(1.0f, r[0]), pack2(r[1], r[2]));
        s_cx[2 * i + 1] = make_ulonglong2(pack2(r[3], r[4]), pack2(r[5], r[6]));
    }
    __syncthreads();

    // 4 target positions per lane (m = mbase + ml + 16k)
    float t0 = ti[(size_t)b * MMM + mbase + ml];
    float t1 = ti[(size_t)b * MMM + mbase + ml + 16];
    float t2 = ti[(size_t)b * MMM + mbase + ml + 32];
    float t3 = ti[(size_t)b * MMM + mbase + ml + 48];

    const int n0 = v * NPS;   // this half-warp's n range [n0, n0+16)

    // accumulators: 4 m x 4 f32x2 channel-pairs
    unsigned long long acc[4][4];
    #pragma unroll
    for (int k = 0; k < 4; k++)
        #pragma unroll
        for (int j = 0; j < 4; j++) acc[k][j] = 0ull;

    if (uni) {
        #pragma unroll
        for (int i = 0; i < NPS / 2; i++) {
            const int np = (n0 >> 1) + i;
            const int n  = n0 + 2 * i;
            float4 ab = s_ab2[np];
            ulonglong2 pa = s_cx[2 * n];
            ulonglong2 qa = s_cx[2 * n + 1];
            ulonglong2 pb = s_cx[2 * n + 2];
            ulonglong2 qb = s_cx[2 * n + 3];

            float wa0 = ex2f(fmaf(ab.y, t0, ab.x));
            float wb0 = ex2f(fmaf(ab.w, t0, ab.z));
            float wa1 = ex2f(fmaf(ab.y, t1, ab.x));
            float wb1 = ex2f(fmaf(ab.w, t1, ab.z));
            float wa2 = ex2f(fmaf(ab.y, t2, ab.x));
            float wb2 = ex2f(fmaf(ab.w, t2, ab.z));
            float wa3 = ex2f(fmaf(ab.y, t3, ab.x));
            float wb3 = ex2f(fmaf(ab.w, t3, ab.z));

            unsigned long long p;
            p = pack2(wa0, wa0);
            ffma2(acc[0][0], p, pa.x); ffma2(acc[0][1], p, pa.y);
            ffma2(acc[0][2], p, qa.x); ffma2(acc[0][3], p, qa.y);
            p = pack2(wb0, wb0);
            ffma2(acc[0][0], p, pb.x); ffma2(acc[0][1], p, pb.y);
            ffma2(acc[0][2], p, qb.x); ffma2(acc[0][3], p, qb.y);
            p = pack2(wa1, wa1);
            ffma2(acc[1][0], p, pa.x); ffma2(acc[1][1], p, pa.y);
            ffma2(acc[1][2], p, qa.x); ffma2(acc[1][3], p, qa.y);
            p = pack2(wb1, wb1);
            ffma2(acc[1][0], p, pb.x); ffma2(acc[1][1], p, pb.y);
            ffma2(acc[1][2], p, qb.x); ffma2(acc[1][3], p, qb.y);
            p = pack2(wa2, wa2);
            ffma2(acc[2][0], p, pa.x); ffma2(acc[2][1], p, pa.y);
            ffma2(acc[2][2], p, qa.x); ffma2(acc[2][3], p, qa.y);
            p = pack2(wb2, wb2);
            ffma2(acc[2][0], p, pb.x); ffma2(acc[2][1], p, pb.y);
            ffma2(acc[2][2], p, qb.x); ffma2(acc[2][3], p, qb.y);
            p = pack2(wa3, wa3);
            ffma2(acc[3][0], p, pa.x); ffma2(acc[3][1], p, pa.y);
            ffma2(acc[3][2], p, qa.x); ffma2(acc[3][3], p, qa.y);
            p = pack2(wb3, wb3);
            ffma2(acc[3][0], p, pb.x); ffma2(acc[3][1], p, pb.y);
            ffma2(acc[3][2], p, qb.x); ffma2(acc[3][3], p, qb.y);
        }
    } else {
        // general path: per-channel scales, same packed accumulators (no extra regs)
        float k2[CC];
        #pragma unroll
        for (int c = 0; c < CC; c++) k2[c] = -0.5f * LOG2E * expf(-2.0f * sigma[c]);
        float tt[4] = {t0, t1, t2, t3};
        for (int i = 0; i < NPS; i++) {
            int n = n0 + i;
            float x = s_abf2[n].x;
            ulonglong2 p = s_cx[2 * n];
            ulonglong2 q = s_cx[2 * n + 1];
            #pragma unroll
            for (int k = 0; k < 4; k++) {
                float diff = x - tt[k];
                float d = diff * diff;
                ffma2(acc[k][0], pack2(ex2f(d * k2[0]), ex2f(d * k2[1])), p.x);
                ffma2(acc[k][1], pack2(ex2f(d * k2[2]), ex2f(d * k2[3])), p.y);
                ffma2(acc[k][2], pack2(ex2f(d * k2[4]), ex2f(d * k2[5])), q.x);
                ffma2(acc[k][3], pack2(ex2f(d * k2[6]), ex2f(d * k2[7])), q.y);
            }
        }
    }

    // unpack + single shfl level: the two half-warps hold the SAME m-set, different n
    {
        #pragma unroll
        for (int k = 0; k < 4; k++) {
            float f[CC];
            unpack2(acc[k][0], f[0], f[1]);
            unpack2(acc[k][1], f[2], f[3]);
            unpack2(acc[k][2], f[4], f[5]);
            unpack2(acc[k][3], f[6], f[7]);
            #pragma unroll
            for (int c = 0; c < CC; c++)
                f[c] += __shfl_xor_sync(0xffffffffu, f[c], 16);
            if (s == 0) {
                int mm = ml + 16 * k;
                #pragma unroll
                for (int c = 0; c < CC; c++) s_part[w][c][mm] = f[c];
            }
        }
    }
    __syncthreads();

    // stage 2: reduce 16 warps; thread = (c = tid>>6, mm = tid&63)
    {
        const int c  = tid >> 6;
        const int mm = tid & 63;
        float acc2 = 0.0f;
        #pragma unroll
        for (int ww = 0; ww < NWARP; ww++) acc2 += s_part[ww][c][mm];
        if (c == 0) s_dens[mm] = acc2;
        __syncthreads();

        float tm = ti[(size_t)b * MMM + mbase + mm];
        float g  = uni ? ex2f(k2u * tm * tm) : 1.0f;
        float d0 = s_dens[mm] * g;                   // true density
        float inv = g / (d0 + 1e-8f);
        s_v[c][mm] = (c == 0) ? d0 : acc2 * inv;
        __syncthreads();
    }

    // stage 3: (8 -> 64) GEMM + bias; thread = (mm = tid>>3, og = tid&7), 8 outputs
    {
        const int mm = tid >> 3;
        const int og = tid & 7;
        float vv[CC];
        #pragma unroll
        for (int c = 0; c < CC; c++) vv[c] = s_v[c][mm];

        float4 r0 = *(const float4*)&s_bias[og * 8];
        float4 r1 = *(const float4*)&s_bias[og * 8 + 4];
        #pragma unroll
        for (int c = 0; c < CC; c++) {
            float4 w0 = *(const float4*)&s_Wt[c][og * 8];
            float4 w1 = *(const float4*)&s_Wt[c][og * 8 + 4];
            r0.x = fmaf(vv[c], w0.x, r0.x);
            r0.y = fmaf(vv[c], w0.y, r0.y);
            r0.z = fmaf(vv[c], w0.z, r0.z);
            r0.w = fmaf(vv[c], w0.w, r0.w);
            r1.x = fmaf(vv[c], w1.x, r1.x);
            r1.y = fmaf(vv[c], w1.y, r1.y);
            r1.z = fmaf(vv[c], w1.z, r1.z);
            r1.w = fmaf(vv[c], w1.w, r1.w);
        }
        float4* outp = (float4*)(out + ((size_t)(b * MMM + mbase + mm)) * COUT + og * 8);
        outp[0] = r0;
        outp[1] = r1;
    }
}

extern "C" void kernel_launch(void* const* d_in, const int* in_sizes, int n_in,
                              void* d_out, int out_size) {
    const float* ci    = (const float*)d_in[0];
    const float* co    = (const float*)d_in[1];
    const float* ti    = (const float*)d_in[2];
    const float* sigma = (const float*)d_in[3];
    const float* W     = (const float*)d_in[4];
    const float* bias  = (const float*)d_in[5];
    float* out = (float*)d_out;

    dim3 grid(BB * (MMM / MPB));   // 256 CTAs
    dim3 block(TPB);               // 512 threads (16 warps, 32 half-warp slices)
    convdeepset_kernel<<<grid, block>>>(ci, co, ti, sigma, W, bias, out);
}

// round 15
// speedup vs baseline: 1.6118x; 1.6118x over previous
#include <cuda_runtime.h>
#include <math.h>

#define BB    16
#define MMM   1024
#define NN    512
#define CC    8
#define COUT  64
#define NWARP 8               // warps per CTA
#define NSUB  (NWARP * 2)     // 16 virtual n-slices (half-warp each)
#define NPS   (NN / NSUB)     // 32 n per half-warp slice
#define MPB   64              // m per CTA (4 per lane, 16 lanes per half)
#define TPB   (32 * NWARP)    // 256 threads

__device__ __forceinline__ float ex2f(float x) {
    float y;
    asm("ex2.approx.ftz.f32 %0, %1;" : "=f"(y) : "f"(x));
    return y;
}
__device__ __forceinline__ unsigned long long pack2(float lo, float hi) {
    unsigned long long r;
    asm("mov.b64 %0, {%1, %2};" : "=l"(r) : "f"(lo), "f"(hi));
    return r;
}
__device__ __forceinline__ void unpack2(unsigned long long v, float& lo, float& hi) {
    asm("mov.b64 {%0, %1}, %2;" : "=f"(lo), "=f"(hi) : "l"(v));
}
__device__ __forceinline__ void ffma2(unsigned long long& d, unsigned long long a, unsigned long long b) {
    asm("fma.rn.f32x2 %0, %1, %2, %0;" : "+l"(d) : "l"(a), "l"(b));
}

__global__ __launch_bounds__(TPB)
void convdeepset_kernel(const float* __restrict__ ci,    // (B,N,1)
                        const float* __restrict__ co,    // (B,N,7)
                        const float* __restrict__ ti,    // (B,M,1)
                        const float* __restrict__ sigma, // (8,)
                        const float* __restrict__ W,     // (64,8)
                        const float* __restrict__ bias,  // (64,)
                        float* __restrict__ out)         // (B,M,64)
{
    __shared__ float4      s_ab2[NN / 2];            // (a_n,b_n,a_{n+1},b_{n+1}) per n-pair (4KB)
    __shared__ ulonglong2  s_cx[NN * 2];             // packed f32x2 channels (16KB)
    __shared__ float       s_part[NWARP][CC][MPB];   // 16KB (post-shfl per-warp partials)
    __shared__ float       s_v[CC][MPB];
    __shared__ float       s_dens[MPB];
    __shared__ float       s_Wt[CC][COUT];
    __shared__ float       s_bias[COUT];

    const int tid  = threadIdx.x;
    const int w    = tid >> 5;
    const int lane = tid & 31;
    const int s    = lane >> 4;          // half-warp n-subslice
    const int ml   = lane & 15;          // local m seed (4 m's: ml + 16k) — SAME for both halves
    const int v    = w * 2 + s;          // virtual slice 0..15
    const int blk  = blockIdx.x;
    const int b    = blk >> 4;           // 16 m-tiles of 64 per batch
    const int mt   = blk & 15;
    const int mbase = mt * MPB;

    // stage W^T + bias (strided)
    for (int i = tid; i < CC * COUT; i += TPB) {
        int o = i / CC, c = i % CC;
        s_Wt[c][o] = W[i];
    }
    if (tid < COUT) s_bias[tid] = bias[tid];

    // uniform-sigma detection
    const float LOG2E = 1.4426950408889634f;
    float sg0 = sigma[0];
    bool uni = true;
    #pragma unroll
    for (int c = 1; c < CC; c++) uni &= (sigma[c] == sg0);
    const float k2u = -0.5f * LOG2E * expf(-2.0f * sg0);

    // stage context rows (2 per thread)
    const float* cib = ci + (size_t)b * NN;
    const float* cob = co + (size_t)b * NN * 7;
    float2* s_abf2 = (float2*)s_ab2;
    for (int i = tid; i < NN; i += TPB) {
        float x = cib[i];
        float2 ab;
        if (uni) { ab.x = k2u * x * x; ab.y = -2.0f * k2u * x; }
        else     { ab.x = x;           ab.y = 0.0f; }
        s_abf2[i] = ab;
        const float* r = cob + i * 7;
        s_cx[2 * i]     = make_ulonglong2(pack2(1.0f, r[0]), pack2(r[1], r[2]));
        s_cx[2 * i + 1] = make_ulonglong2(pack2(r[3], r[4]), pack2(r[5], r[6]));
    }
    __syncthreads();

    // 4 target positions per lane
    float t0 = ti[(size_t)b * MMM + mbase + ml];
    float t1 = ti[(size_t)b * MMM + mbase + ml + 16];
    float t2 = ti[(size_t)b * MMM + mbase + ml + 32];
    float t3 = ti[(size_t)b * MMM + mbase + ml + 48];

    const int n0 = v * NPS;   // this half-warp's n range [n0, n0+32)

    // accumulators: 4 m x 4 f32x2 channel-pairs
    unsigned long long acc[4][4];
    #pragma unroll
    for (int k = 0; k < 4; k++)
        #pragma unroll
        for (int j = 0; j < 4; j++) acc[k][j] = 0ull;

    if (uni) {
        #pragma unroll 8
        for (int i = 0; i < NPS / 2; i++) {
            const int np = (n0 >> 1) + i;
            const int n  = n0 + 2 * i;
            float4 ab = s_ab2[np];
            ulonglong2 pa = s_cx[2 * n];
            ulonglong2 qa = s_cx[2 * n + 1];
            ulonglong2 pb = s_cx[2 * n + 2];
            ulonglong2 qb = s_cx[2 * n + 3];

            float wa0 = ex2f(fmaf(ab.y, t0, ab.x));
            float wb0 = ex2f(fmaf(ab.w, t0, ab.z));
            float wa1 = ex2f(fmaf(ab.y, t1, ab.x));
            float wb1 = ex2f(fmaf(ab.w, t1, ab.z));
            float wa2 = ex2f(fmaf(ab.y, t2, ab.x));
            float wb2 = ex2f(fmaf(ab.w, t2, ab.z));
            float wa3 = ex2f(fmaf(ab.y, t3, ab.x));
            float wb3 = ex2f(fmaf(ab.w, t3, ab.z));

            unsigned long long p;
            p = pack2(wa0, wa0);
            ffma2(acc[0][0], p, pa.x); ffma2(acc[0][1], p, pa.y);
            ffma2(acc[0][2], p, qa.x); ffma2(acc[0][3], p, qa.y);
            p = pack2(wb0, wb0);
            ffma2(acc[0][0], p, pb.x); ffma2(acc[0][1], p, pb.y);
            ffma2(acc[0][2], p, qb.x); ffma2(acc[0][3], p, qb.y);
            p = pack2(wa1, wa1);
            ffma2(acc[1][0], p, pa.x); ffma2(acc[1][1], p, pa.y);
            ffma2(acc[1][2], p, qa.x); ffma2(acc[1][3], p, qa.y);
            p = pack2(wb1, wb1);
            ffma2(acc[1][0], p, pb.x); ffma2(acc[1][1], p, pb.y);
            ffma2(acc[1][2], p, qb.x); ffma2(acc[1][3], p, qb.y);
            p = pack2(wa2, wa2);
            ffma2(acc[2][0], p, pa.x); ffma2(acc[2][1], p, pa.y);
            ffma2(acc[2][2], p, qa.x); ffma2(acc[2][3], p, qa.y);
            p = pack2(wb2, wb2);
            ffma2(acc[2][0], p, pb.x); ffma2(acc[2][1], p, pb.y);
            ffma2(acc[2][2], p, qb.x); ffma2(acc[2][3], p, qb.y);
            p = pack2(wa3, wa3);
            ffma2(acc[3][0], p, pa.x); ffma2(acc[3][1], p, pa.y);
            ffma2(acc[3][2], p, qa.x); ffma2(acc[3][3], p, qa.y);
            p = pack2(wb3, wb3);
            ffma2(acc[3][0], p, pb.x); ffma2(acc[3][1], p, pb.y);
            ffma2(acc[3][2], p, qb.x); ffma2(acc[3][3], p, qb.y);
        }
    } else {
        // general path: per-channel scales, same packed accumulators
        float k2[CC];
        #pragma unroll
        for (int c = 0; c < CC; c++) k2[c] = -0.5f * LOG2E * expf(-2.0f * sigma[c]);
        float tt[4] = {t0, t1, t2, t3};
        for (int i = 0; i < NPS; i++) {
            int n = n0 + i;
            float x = s_abf2[n].x;
            ulonglong2 p = s_cx[2 * n];
            ulonglong2 q = s_cx[2 * n + 1];
            #pragma unroll
            for (int k = 0; k < 4; k++) {
                float diff = x - tt[k];
                float d = diff * diff;
                ffma2(acc[k][0], pack2(ex2f(d * k2[0]), ex2f(d * k2[1])), p.x);
                ffma2(acc[k][1], pack2(ex2f(d * k2[2]), ex2f(d * k2[3])), p.y);
                ffma2(acc[k][2], pack2(ex2f(d * k2[4]), ex2f(d * k2[5])), q.x);
                ffma2(acc[k][3], pack2(ex2f(d * k2[6]), ex2f(d * k2[7])), q.y);
            }
        }
    }

    // unpack + shfl(16): the two half-warps hold the SAME m-set, different n
    {
        #pragma unroll
        for (int k = 0; k < 4; k++) {
            float f[CC];
            unpack2(acc[k][0], f[0], f[1]);
            unpack2(acc[k][1], f[2], f[3]);
            unpack2(acc[k][2], f[4], f[5]);
            unpack2(acc[k][3], f[6], f[7]);
            #pragma unroll
            for (int c = 0; c < CC; c++)
                f[c] += __shfl_xor_sync(0xffffffffu, f[c], 16);
            if (s == 0) {
                int mm = ml + 16 * k;
                #pragma unroll
                for (int c = 0; c < CC; c++) s_part[w][c][mm] = f[c];
            }
        }
    }
    __syncthreads();

    // stage 2: reduce 8 warps; each thread handles 2 (c,mm) cells
    {
        #pragma unroll
        for (int rep = 0; rep < 2; rep++) {
            int idx = tid + rep * TPB;          // 0..511
            int c  = idx >> 6;
            int mm = idx & 63;
            float acc2 = 0.0f;
            #pragma unroll
            for (int ww = 0; ww < NWARP; ww++) acc2 += s_part[ww][c][mm];
            if (c == 0) s_dens[mm] = acc2;
            else        s_v[c][mm] = acc2;      // raw sums
        }
        __syncthreads();
        #pragma unroll
        for (int rep = 0; rep < 2; rep++) {
            int idx = tid + rep * TPB;
            int c  = idx >> 6;
            int mm = idx & 63;
            float tm = ti[(size_t)b * MMM + mbase + mm];
            float g  = uni ? ex2f(k2u * tm * tm) : 1.0f;
            float d0 = s_dens[mm] * g;          // true density
            float inv = g / (d0 + 1e-8f);
            if (c == 0) s_v[0][mm] = d0;
            else        s_v[c][mm] = s_v[c][mm] * inv;
        }
        __syncthreads();
    }

    // stage 3: (8 -> 64) GEMM + bias; thread = (mm = tid>>2, og = tid&3), 16 outputs
    {
        const int mm = tid >> 2;
        const int og = tid & 3;
        float vv[CC];
        #pragma unroll
        for (int c = 0; c < CC; c++) vv[c] = s_v[c][mm];

        float4* outp = (float4*)(out + ((size_t)(b * MMM + mbase + mm)) * COUT + og * 16);
        #pragma unroll
        for (int j = 0; j < 4; j++) {
            int o4 = og * 4 + j;
            float4 r = *(const float4*)&s_bias[o4 * 4];
            #pragma unroll
            for (int c = 0; c < CC; c++) {
                float4 w4 = *(const float4*)&s_Wt[c][o4 * 4];
                r.x = fmaf(vv[c], w4.x, r.x);
                r.y = fmaf(vv[c], w4.y, r.y);
                r.z = fmaf(vv[c], w4.z, r.z);
                r.w = fmaf(vv[c], w4.w, r.w);
            }
            outp[j] = r;
        }
    }
}

extern "C" void kernel_launch(void* const* d_in, const int* in_sizes, int n_in,
                              void* d_out, int out_size) {
    const float* ci    = (const float*)d_in[0];
    const float* co    = (const float*)d_in[1];
    const float* ti    = (const float*)d_in[2];
    const float* sigma = (const float*)d_in[3];
    const float* W     = (const float*)d_in[4];
    const float* bias  = (const float*)d_in[5];
    float* out = (float*)d_out;

    dim3 grid(BB * (MMM / MPB));   // 256 CTAs
    dim3 block(TPB);               // 256 threads (8 warps, 16 half-warp n-slices)
    convdeepset_kernel<<<grid, block>>>(ci, co, ti, sigma, W, bias, out);
}